// round 11
// baseline (speedup 1.0000x reference)
#include <cuda_runtime.h>

// Problem geometry (fixed by the dataset):
//   y: [1,512,512,8,8] f32 = 16,777,216 elems
//   c: [2,256,256,8,8] f32 =  8,388,608 elems (2 channels x 4,194,304)
// Output: y then c concatenated, 25,165,824 f32.
//
// Single fused launch, 6,144 blocks x 256 threads, 4 float4 per thread
// (each block owns 1024 consecutive float4s; MLP optimum measured: 4).
//
// Cache policy (graph-replay steady state; L2 is NOT flushed between
// replays and inputs total 100.6 MB < 126 MB L2):
//   - input loads : ld.global.L2::cache_hint with a createpolicy
//                   fractional L2::evict_last policy -> inputs biased to
//                   stay L2-resident across replays.
//   - output stores: st.global.cs (evict-first) -> write stream does not
//                   displace the resident inputs.
//
//   blocks [0, 512)      : extra duty — DC reduction into g_dc_sum.
//   blocks [0, 4096)     : y elementwise.
//   blocks [4096, 6144)  : c elementwise; thread 0 polls g_red_cnt (done
//                          waves earlier), broadcasts mean via shared mem.
//   Last finished c-block resets globals for the next graph replay.

#define CMIN  (-1024.0f)
#define CMAX  (1016.0f)
#define FACT  (1.9f)

static const int   NY4       = 4194304;    // y float4 count
static const int   N_Y_BLK   = 4096;       // pure-y blocks
static const int   N_RED_BLK = 512;        // reducer blocks (256 DC each)
static const int   N_C_BLK   = 2048;       // c blocks
static const float INV_CNT   = 1.0f / 65536.0f;

__device__ float g_dc_sum[2];
__device__ int   g_red_cnt;
__device__ int   g_c_done;

// L2 evict_last access policy (created once per thread; uniform, hoisted).
__device__ __forceinline__ unsigned long long mk_keep_policy() {
    unsigned long long pol;
    asm volatile("createpolicy.fractional.L2::evict_last.b64 %0, 1.0;"
                 : "=l"(pol));
    return pol;
}

// 16-byte load with L2 evict_last cache hint (keep inputs L2-resident).
__device__ __forceinline__ float4 ld_keep(const float4* p,
                                          unsigned long long pol) {
    float4 v;
    asm volatile("ld.global.L2::cache_hint.v4.f32 {%0,%1,%2,%3}, [%4], %5;"
                 : "=f"(v.x), "=f"(v.y), "=f"(v.z), "=f"(v.w)
                 : "l"(p), "l"(pol));
    return v;
}

__device__ __forceinline__ float clampf(float v) {
    return fminf(fmaxf(v, CMIN), CMAX);
}

__device__ __forceinline__ float4 y_op(float4 v) {
    v.x = clampf(clampf(v.x) * FACT);
    v.y = clampf(clampf(v.y) * FACT);
    v.z = clampf(clampf(v.z) * FACT);
    v.w = clampf(clampf(v.w) * FACT);
    return v;
}

__device__ __forceinline__ float4 c_op(float4 v, int j, float blend) {
    v.x = clampf(v.x) * FACT;
    v.y = clampf(v.y) * FACT;
    v.z = clampf(v.z) * FACT;
    v.w = clampf(v.w) * FACT;
    if ((j & 15) == 0) v.x += blend;   // elem j*4 is a DC coeff (idx%64==0)
    v.x = clampf(v.x);
    v.y = clampf(v.y);
    v.z = clampf(v.z);
    v.w = clampf(v.w);
    return v;
}

__global__ void __launch_bounds__(256) fused_kernel(
    const float4* __restrict__ y, const float4* __restrict__ c,
    float4* __restrict__ oy, float4* __restrict__ oc)
{
    __shared__ float s_warp[8];
    __shared__ float s_mean;

    unsigned long long pol = mk_keep_policy();

    // ---- Extra duty: DC reduction on first 512 blocks (wave 1) ----
    if (blockIdx.x < N_RED_BLK) {
        int idx = blockIdx.x * 256 + threadIdx.x;   // 0 .. 131071
        int ch  = idx >> 16;                        // constant per block
        // DC coeff idx lives at c-element idx*64 == float4 idx*16, comp .x
        float v = clampf(ld_keep(&c[idx * 16], pol).x);

        #pragma unroll
        for (int off = 16; off > 0; off >>= 1)
            v += __shfl_down_sync(0xffffffffu, v, off);
        if ((threadIdx.x & 31) == 0) s_warp[threadIdx.x >> 5] = v;
        __syncthreads();
        if (threadIdx.x < 8) {
            float w = s_warp[threadIdx.x];
            #pragma unroll
            for (int off = 4; off > 0; off >>= 1)
                w += __shfl_down_sync(0xffu, w, off);
            if (threadIdx.x == 0) {
                atomicAdd(&g_dc_sum[ch], w);
                __threadfence();
                atomicAdd(&g_red_cnt, 1);
            }
        }
    }

    // Block owns 1024 consecutive float4s; thread takes tid + {0,256,512,768}.
    int i0 = blockIdx.x * 1024 + threadIdx.x;

    if (blockIdx.x < N_Y_BLK) {
        // ---- pure-y block: 4 front-batched evict_last loads ----
        float4 a = ld_keep(&y[i0],       pol);
        float4 b = ld_keep(&y[i0 + 256], pol);
        float4 d = ld_keep(&y[i0 + 512], pol);
        float4 e = ld_keep(&y[i0 + 768], pol);
        __stcs(&oy[i0],       y_op(a));
        __stcs(&oy[i0 + 256], y_op(b));
        __stcs(&oy[i0 + 512], y_op(d));
        __stcs(&oy[i0 + 768], y_op(e));
    } else {
        // ---- pure-c block ----
        int j0 = i0 - NY4;                   // 0 .. NC4-1
        int ch = j0 >> 20;                   // constant per block (1M-aligned)

        // One thread waits (reduction finished waves ago) and reads the mean
        // exactly once; everyone else gets it through shared memory.
        if (threadIdx.x == 0) {
            while (*((volatile int*)&g_red_cnt) != N_RED_BLK) { }
            s_mean = (*((volatile float*)&g_dc_sum[ch])) * INV_CNT;
        }

        float4 a = ld_keep(&c[j0],       pol);   // loads overlap the wait
        float4 b = ld_keep(&c[j0 + 256], pol);
        float4 d = ld_keep(&c[j0 + 512], pol);
        float4 e = ld_keep(&c[j0 + 768], pol);
        __syncthreads();
        float blend = (1.0f - FACT) * s_mean;

        __stcs(&oc[j0],       c_op(a, j0,       blend));
        __stcs(&oc[j0 + 256], c_op(b, j0 + 256, blend));
        __stcs(&oc[j0 + 512], c_op(d, j0 + 512, blend));
        __stcs(&oc[j0 + 768], c_op(e, j0 + 768, blend));

        // ---- reset globals for next graph replay (last finished c-block) ----
        __syncthreads();
        if (threadIdx.x == 0) {
            int old = atomicAdd(&g_c_done, 1);
            if (old == N_C_BLK - 1) {
                *((volatile float*)&g_dc_sum[0]) = 0.0f;
                *((volatile float*)&g_dc_sum[1]) = 0.0f;
                *((volatile int*)&g_red_cnt)     = 0;
                *((volatile int*)&g_c_done)      = 0;
                __threadfence();
            }
        }
    }
}

extern "C" void kernel_launch(void* const* d_in, const int* in_sizes, int n_in,
                              void* d_out, int out_size) {
    const float4* y = (const float4*)d_in[0];
    const float4* c = (const float4*)d_in[1];
    float4* oy = (float4*)d_out;
    float4* oc = (float4*)d_out + NY4;

    unsigned grid = (unsigned)(N_Y_BLK + N_C_BLK);   // 6,144 blocks
    fused_kernel<<<grid, 256>>>(y, c, oy, oc);
}

// round 12
// speedup vs baseline: 1.0703x; 1.0703x over previous
#include <cuda_runtime.h>

// Problem geometry (fixed by the dataset):
//   y: [1,512,512,8,8] f32 = 16,777,216 elems
//   c: [2,256,256,8,8] f32 =  8,388,608 elems (2 channels x 4,194,304)
// Output: y then c concatenated, 25,165,824 f32.
//
// FINAL CONFIG (best measured: 34.24us; session ledger in commit log):
// Single fused launch, 6,144 blocks x 256 threads, 4 float4 per thread
// (each block owns 1024 consecutive float4s).
// Measured MLP sweep: 2 -> 30.3us, 4 -> 27.3-28.2us, 8 -> 33.3us (regs/occ
// + L1tex queue). Persistent grid: neutral. L2 evict_last residency: worse.
//   blocks [0, 512)      : extra duty — DC reduction (one clamped DC/thread),
//                          atomicAdd into g_dc_sum, bump g_red_cnt. Wave 1.
//   blocks [0, 4096)     : y elementwise (NY4/1024 == 4096 exactly).
//   blocks [4096, 6144)  : c elementwise (start waves later). Thread 0 polls
//                          g_red_cnt (long done), reads the mean once,
//                          broadcasts via shared memory (per-thread volatile
//                          reads of one global address cost ~15us in L2
//                          serialization — measured in R3).
//   Bulk stream is touch-once: __ldcs / __stcs.
//   Last finished c-block resets globals for the next graph replay.

#define CMIN  (-1024.0f)
#define CMAX  (1016.0f)
#define FACT  (1.9f)

static const int   NY4       = 4194304;    // y float4 count
static const int   N_Y_BLK   = 4096;       // pure-y blocks
static const int   N_RED_BLK = 512;        // reducer blocks (256 DC each)
static const int   N_C_BLK   = 2048;       // c blocks
static const float INV_CNT   = 1.0f / 65536.0f;

__device__ float g_dc_sum[2];
__device__ int   g_red_cnt;
__device__ int   g_c_done;

__device__ __forceinline__ float clampf(float v) {
    return fminf(fmaxf(v, CMIN), CMAX);
}

__device__ __forceinline__ float4 y_op(float4 v) {
    v.x = clampf(clampf(v.x) * FACT);
    v.y = clampf(clampf(v.y) * FACT);
    v.z = clampf(clampf(v.z) * FACT);
    v.w = clampf(clampf(v.w) * FACT);
    return v;
}

__device__ __forceinline__ float4 c_op(float4 v, int j, float blend) {
    v.x = clampf(v.x) * FACT;
    v.y = clampf(v.y) * FACT;
    v.z = clampf(v.z) * FACT;
    v.w = clampf(v.w) * FACT;
    if ((j & 15) == 0) v.x += blend;   // elem j*4 is a DC coeff (idx%64==0)
    v.x = clampf(v.x);
    v.y = clampf(v.y);
    v.z = clampf(v.z);
    v.w = clampf(v.w);
    return v;
}

__global__ void __launch_bounds__(256) fused_kernel(
    const float4* __restrict__ y, const float4* __restrict__ c,
    float4* __restrict__ oy, float4* __restrict__ oc)
{
    __shared__ float s_warp[8];
    __shared__ float s_mean;

    // ---- Extra duty: DC reduction on first 512 blocks (wave 1) ----
    if (blockIdx.x < N_RED_BLK) {
        int idx = blockIdx.x * 256 + threadIdx.x;   // 0 .. 131071
        int ch  = idx >> 16;                        // constant per block
        // DC coeff idx lives at c-element idx*64 == float4 idx*16, comp .x
        // Default (caching) load: c-blocks re-read these lines later.
        float v = clampf(c[idx * 16].x);

        #pragma unroll
        for (int off = 16; off > 0; off >>= 1)
            v += __shfl_down_sync(0xffffffffu, v, off);
        if ((threadIdx.x & 31) == 0) s_warp[threadIdx.x >> 5] = v;
        __syncthreads();
        if (threadIdx.x < 8) {
            float w = s_warp[threadIdx.x];
            #pragma unroll
            for (int off = 4; off > 0; off >>= 1)
                w += __shfl_down_sync(0xffu, w, off);
            if (threadIdx.x == 0) {
                atomicAdd(&g_dc_sum[ch], w);
                __threadfence();
                atomicAdd(&g_red_cnt, 1);
            }
        }
    }

    // Block owns 1024 consecutive float4s; thread takes tid + {0,256,512,768}.
    int i0 = blockIdx.x * 1024 + threadIdx.x;

    if (blockIdx.x < N_Y_BLK) {
        // ---- pure-y block: 4 front-batched streaming loads ----
        float4 a = __ldcs(&y[i0]);
        float4 b = __ldcs(&y[i0 + 256]);
        float4 d = __ldcs(&y[i0 + 512]);
        float4 e = __ldcs(&y[i0 + 768]);
        __stcs(&oy[i0],       y_op(a));
        __stcs(&oy[i0 + 256], y_op(b));
        __stcs(&oy[i0 + 512], y_op(d));
        __stcs(&oy[i0 + 768], y_op(e));
    } else {
        // ---- pure-c block ----
        int j0 = i0 - NY4;                   // 0 .. NC4-1
        int ch = j0 >> 20;                   // constant per block (1M-aligned)

        // One thread waits (reduction finished waves ago) and reads the mean
        // exactly once; everyone else gets it through shared memory.
        if (threadIdx.x == 0) {
            while (*((volatile int*)&g_red_cnt) != N_RED_BLK) { }
            s_mean = (*((volatile float*)&g_dc_sum[ch])) * INV_CNT;
        }

        float4 a = __ldcs(&c[j0]);           // loads overlap the wait
        float4 b = __ldcs(&c[j0 + 256]);
        float4 d = __ldcs(&c[j0 + 512]);
        float4 e = __ldcs(&c[j0 + 768]);
        __syncthreads();
        float blend = (1.0f - FACT) * s_mean;

        __stcs(&oc[j0],       c_op(a, j0,       blend));
        __stcs(&oc[j0 + 256], c_op(b, j0 + 256, blend));
        __stcs(&oc[j0 + 512], c_op(d, j0 + 512, blend));
        __stcs(&oc[j0 + 768], c_op(e, j0 + 768, blend));

        // ---- reset globals for next graph replay (last finished c-block) ----
        __syncthreads();
        if (threadIdx.x == 0) {
            int old = atomicAdd(&g_c_done, 1);
            if (old == N_C_BLK - 1) {
                *((volatile float*)&g_dc_sum[0]) = 0.0f;
                *((volatile float*)&g_dc_sum[1]) = 0.0f;
                *((volatile int*)&g_red_cnt)     = 0;
                *((volatile int*)&g_c_done)      = 0;
                __threadfence();
            }
        }
    }
}

extern "C" void kernel_launch(void* const* d_in, const int* in_sizes, int n_in,
                              void* d_out, int out_size) {
    const float4* y = (const float4*)d_in[0];
    const float4* c = (const float4*)d_in[1];
    float4* oy = (float4*)d_out;
    float4* oc = (float4*)d_out + NY4;

    unsigned grid = (unsigned)(N_Y_BLK + N_C_BLK);   // 6,144 blocks
    fused_kernel<<<grid, 256>>>(y, c, oy, oc);
}